// round 6
// baseline (speedup 1.0000x reference)
#include <cuda_runtime.h>

// Problem constants
#define BF_TOT  (16 * 4096)      // B * F = 65536
#define PAIRS   6                // 12 data symbols -> 6 STBC pairs
#define NBITS0  3145728          // BF_TOT * 48
#define NGAIN   786432           // BF_TOT * 12

__device__ __forceinline__ float2 cmul (float2 a, float2 b){ return make_float2(a.x*b.x - a.y*b.y, a.x*b.y + a.y*b.x); }
__device__ __forceinline__ float2 cmulc(float2 a, float2 b){ /* conj(a)*b */ return make_float2(a.x*b.x + a.y*b.y, a.x*b.y - a.y*b.x); }
__device__ __forceinline__ float2 cadd (float2 a, float2 b){ return make_float2(a.x+b.x, a.y+b.y); }
__device__ __forceinline__ float2 csub (float2 a, float2 b){ return make_float2(a.x-b.x, a.y-b.y); }
__device__ __forceinline__ float2 cscl (float2 a, float s){ return make_float2(a.x*s, a.y*s); }
__device__ __forceinline__ float2 cconj(float2 a){ return make_float2(a.x, -a.y); }

// 16-QAM Gray hard decision (max-log equivalent).
__device__ __forceinline__ void hd16(float2 y, float2& pt, int& bits){
    const float C1 = 0.31622776601683794f;   // 1/sqrt(10)
    const float C3 = 0.9486832980505138f;    // 3/sqrt(10)
    const float T  = 0.6324555320336759f;    // 2/sqrt(10)
    int b0 = (y.x < 0.0f);
    int b1 = (y.y < 0.0f);
    int b2 = (fabsf(y.x) > T);
    int b3 = (fabsf(y.y) > T);
    float xi = b2 ? C3 : C1; if (b0) xi = -xi;
    float xq = b3 ? C3 : C1; if (b1) xq = -xq;
    pt = make_float2(xi, xq);
    bits = b0 | (b1 << 1) | (b2 << 2) | (b3 << 3);
}

// 2-step xor butterfly over each 4-lane group (result broadcast within group)
#define RED4(v) do { \
    v += __shfl_xor_sync(0xffffffffu, v, 1);  \
    v += __shfl_xor_sync(0xffffffffu, v, 2);  \
} while (0)

// Per-antenna Gram/rhs accumulation from raw channel float4s.
#define GRAM_ACC(hrA_, hiA_, hrB_, hiB_, yA_, yB_) do {                         \
    float2 a_ = make_float2(0.5f*((hrA_).x+(hrB_).x), 0.5f*((hiA_).x+(hiB_).x)); \
    float2 b_ = make_float2(0.5f*((hrA_).y+(hrB_).y), 0.5f*((hiA_).y+(hiB_).y)); \
    float2 c_ = make_float2(0.5f*((hrA_).z+(hrB_).z), 0.5f*((hiA_).z+(hiB_).z)); \
    float2 d_ = make_float2(0.5f*((hrA_).w+(hrB_).w), 0.5f*((hiA_).w+(hiB_).w)); \
    alpha += a_.x*a_.x + a_.y*a_.y + b_.x*b_.x + b_.y*b_.y;                      \
    beta  += c_.x*c_.x + c_.y*c_.y + d_.x*d_.x + d_.y*d_.y;                      \
    gam = cadd(gam, cadd(cmulc(a_, c_), cmul(b_, cconj(d_))));                   \
    del = cadd(del, csub(cmulc(a_, d_), cmul(b_, cconj(c_))));                   \
    float2 z2_ = cconj(yB_);                                                     \
    u0 = cadd(u0, cadd(cmulc(a_, (yA_)), cmul(b_, z2_)));                        \
    u1 = cadd(u1, csub(cmulc(b_, (yA_)), cmul(a_, z2_)));                        \
    u2 = cadd(u2, cadd(cmulc(c_, (yA_)), cmul(d_, z2_)));                        \
    u3 = cadd(u3, csub(cmulc(d_, (yA_)), cmul(c_, z2_)));                        \
} while (0)

// Per-antenna SIC from (reloaded) raw channel float4s.
#define SIC_ACC(hrA_, hiA_, hrB_, hiB_, yA_, yB_) do {                           \
    float2 cbA0_, cbA1_, cbB0_, cbB1_, g0_, g1_;                                 \
    if (c0) {                                                                    \
        cbA0_ = make_float2((hrA_).x, (hiA_).x); cbA1_ = make_float2((hrA_).y, (hiA_).y); \
        cbB0_ = make_float2((hrB_).x, (hiB_).x); cbB1_ = make_float2((hrB_).y, (hiB_).y); \
        g0_ = make_float2(0.5f*((hrA_).z+(hrB_).z), 0.5f*((hiA_).z+(hiB_).z));   \
        g1_ = make_float2(0.5f*((hrA_).w+(hrB_).w), 0.5f*((hiA_).w+(hiB_).w));   \
    } else {                                                                     \
        cbA0_ = make_float2((hrA_).z, (hiA_).z); cbA1_ = make_float2((hrA_).w, (hiA_).w); \
        cbB0_ = make_float2((hrB_).z, (hiB_).z); cbB1_ = make_float2((hrB_).w, (hiB_).w); \
        g0_ = make_float2(0.5f*((hrA_).x+(hrB_).x), 0.5f*((hiA_).x+(hiB_).x));   \
        g1_ = make_float2(0.5f*((hrA_).y+(hrB_).y), 0.5f*((hiA_).y+(hiB_).y));   \
    }                                                                            \
    float2 eA_ = cadd(cmul(cbA0_, bx0), cmul(cbA1_, bx1));                       \
    float2 eB_ = cadd(cmul(cbB0_, mcbx1), cmul(cbB1_, cbx0));                    \
    float2 rnA_ = csub((yA_), eA_);                                              \
    float2 rnBc_ = cconj(csub((yB_), eB_));                                      \
    t0 = cadd(t0, cadd(cmulc(g0_, rnA_), cmul(g1_, rnBc_)));                     \
    t1 = cadd(t1, csub(cmulc(g1_, rnA_), cmul(g0_, rnBc_)));                     \
} while (0)

#define STASH_STRIDE 17   // float4 units; banks (68*l + 4*slot)%32 -> conflict-free phases
#define SMEM_BYTES (256 * STASH_STRIDE * 16)

__global__ void __launch_bounds__(256, 3)
mc_ncjt_kernel(const float* __restrict__ ryR, const float* __restrict__ ryI,
               const float* __restrict__ hR,  const float* __restrict__ hI,
               float* __restrict__ out)
{
    extern __shared__ float4 stash[];   // [256][STASH_STRIDE]
    const int tid  = threadIdx.x;
    const int lane = tid & 31;
    const int warp = blockIdx.x * 8 + (tid >> 5);
    const int q    = lane >> 2;       // which pair within the warp (8 pairs/warp)
    const int j    = lane & 3;        // 4 lanes per pair; lane owns antennas j+4k, k=0..3

    float4* st = stash + tid * STASH_STRIDE;

    const int P  = warp * 8 + q;      // global STBC-pair index, exact grid
    const int bf = P / PAIRS;
    const int p  = P - bf * PAIRS;

    // data-symbol pairs: (0,1)(3,4)(5,6)(7,8)(9,10)(12,13)
    const int sA = 2*p + (p >= 1) + (p >= 5);
    const int sB = sA + 1;

    const float4* hR4 = (const float4*)hR;
    const float4* hI4 = (const float4*)hI;
    const size_t h4base = (size_t)bf * 224;          // bf * S*NRX*NTX / 4
    const size_t iA = h4base + (size_t)sA*16 + j;
    const size_t iB = h4base + (size_t)sB*16 + j;
    const size_t rb = (size_t)bf * 224;              // bf * S*NRX

    float alpha = 0.f, beta = 0.f;
    float2 gam = make_float2(0,0), del = make_float2(0,0);
    float2 u0 = make_float2(0,0), u1 = make_float2(0,0);
    float2 u2 = make_float2(0,0), u3 = make_float2(0,0);

    float2 yA[4], yB[4];              // stays in registers through the solve
    #pragma unroll
    for (int k = 0; k < 4; k++) {
        float4 hrA = hR4[iA + 4*k], hiA = hI4[iA + 4*k];
        float4 hrB = hR4[iB + 4*k], hiB = hI4[iB + 4*k];
        st[4*k + 0] = hrA; st[4*k + 1] = hiA;
        st[4*k + 2] = hrB; st[4*k + 3] = hiB;
        yA[k] = make_float2(ryR[rb + sA*16 + j + 4*k], ryI[rb + sA*16 + j + 4*k]);
        yB[k] = make_float2(ryR[rb + sB*16 + j + 4*k], ryI[rb + sB*16 + j + 4*k]);
        GRAM_ACC(hrA, hiA, hrB, hiB, yA[k], yB[k]);
    }

    // ---- 4-lane reductions (broadcast within pair group) ----
    RED4(alpha); RED4(beta);
    RED4(gam.x); RED4(gam.y); RED4(del.x); RED4(del.y);
    RED4(u0.x);  RED4(u0.y);  RED4(u1.x);  RED4(u1.y);
    RED4(u2.x);  RED4(u2.y);  RED4(u3.x);  RED4(u3.y);

    // ---- closed-form Schur solve of the structured 4x4 system ----
    const float e      = gam.x*gam.x + gam.y*gam.y + del.x*del.x + del.y*del.y;
    const float invden = 1.0f / (alpha * beta - e);
    const float invA   = 1.0f / alpha;
    float2 t2 = csub(cscl(u2, alpha), csub(cmulc(gam, u0), cmul(del, u1)));
    float2 t3 = csub(cscl(u3, alpha), cadd(cmulc(del, u0), cmul(gam, u1)));
    float2 s2 = cscl(t2, invden);
    float2 s3 = cscl(t3, invden);
    float2 s0 = cscl(csub(u0, cadd(cmul(gam, s2), cmul(del, s3))), invA);
    float2 s1 = cscl(cadd(u1, csub(cmul(cconj(del), s2), cmul(cconj(gam), s3))), invA);

    const bool c0 = (alpha >= beta);

    float2 px0, px1, px2, px3; int ib0, ib1, ib2, ib3;
    hd16(s0, px0, ib0); hd16(s1, px1, ib1);
    hd16(s2, px2, ib2); hd16(s3, px3, ib3);

    float2 bx0 = c0 ? px0 : px2;     // better-stream decisions (sym A, sym B)
    float2 bx1 = c0 ? px1 : px3;
    float2 mcbx1 = make_float2(-bx1.x, bx1.y);     // -conj(bx1)
    float2 cbx0  = cconj(bx0);

    // ---- SIC over this lane's 4 antennas (h reloaded from smem, y from regs) ----
    float2 t0 = make_float2(0,0), t1 = make_float2(0,0);
    #pragma unroll
    for (int k = 0; k < 4; k++) {
        float4 hrA = st[4*k + 0], hiA = st[4*k + 1];
        float4 hrB = st[4*k + 2], hiB = st[4*k + 3];
        SIC_ACC(hrA, hiA, hrB, hiB, yA[k], yB[k]);
    }
    RED4(t0.x); RED4(t0.y); RED4(t1.x); RED4(t1.y);

    const float invG = 1.0f / (c0 ? beta : alpha);
    float2 pn0, pn1; int ibn0, ibn1;
    hd16(cscl(t0, invG), pn0, ibn0);
    hd16(cscl(t1, invG), pn1, ibn1);

    // final stream assignments
    const int bb0 = c0 ? ib0 : ib2;   // better bits sym A
    const int bb1 = c0 ? ib1 : ib3;   // better bits sym B
    const int b0A = c0 ? bb0  : ibn0; // bits0 (stream 0)
    const int b0B = c0 ? bb1  : ibn1;
    const int b1A = c0 ? ibn0 : bb0;  // bits1 (stream 1)
    const int b1B = c0 ? ibn1 : bb1;

    // ---- outputs: bits0 | bits1 | gains0 | gains1 | nvar ----
    float* bits0 = out;
    float* bits1 = out + NBITS0;
    float* g0out = out + 2 * NBITS0;
    float* g1out = out + 2 * NBITS0 + NGAIN;

    const int sym0 = 2 * p;
    const size_t bbase = (size_t)bf*48 + sym0*4;     // float4-aligned

    {   // every lane (j=0..3) writes one float4 of bits
        int nib = (j == 0) ? b0A : (j == 1) ? b0B : (j == 2) ? b1A : b1B;
        float4 v = make_float4((float)( nib       & 1), (float)((nib >> 1) & 1),
                               (float)((nib >> 2) & 1), (float)((nib >> 3) & 1));
        float* base = (j < 2) ? bits0 : bits1;
        *(float4*)(base + bbase + ((j & 1) << 2)) = v;
    }
    if (j == 0) {
        *(float2*)(g0out + (size_t)bf*12 + sym0) = make_float2(alpha, alpha);
    } else if (j == 1) {
        *(float2*)(g1out + (size_t)bf*12 + sym0) = make_float2(beta, beta);
    }

    if (blockIdx.x == 0 && threadIdx.x == 0)
        out[2 * (NBITS0 + NGAIN)] = 0.4f;    // nvar scalar
}

extern "C" void kernel_launch(void* const* d_in, const int* in_sizes, int n_in,
                              void* d_out, int out_size) {
    const float* ryR = (const float*)d_in[0];
    const float* ryI = (const float*)d_in[1];
    const float* hR  = (const float*)d_in[2];
    const float* hI  = (const float*)d_in[3];
    float* out = (float*)d_out;

    // dynamic smem > 48KB needs opt-in (idempotent; safe under graph capture)
    cudaFuncSetAttribute(mc_ncjt_kernel,
                         cudaFuncAttributeMaxDynamicSharedMemorySize, SMEM_BYTES);

    // total pairs = 65536*6 = 393216; 8 pairs/warp, 8 warps/block -> 6144 blocks
    const int total_pairs = BF_TOT * PAIRS;
    const int blocks = total_pairs / 64;   // 64 pairs per 256-thread block
    mc_ncjt_kernel<<<blocks, 256, SMEM_BYTES>>>(ryR, ryI, hR, hI, out);
}

// round 8
// speedup vs baseline: 1.5557x; 1.5557x over previous
#include <cuda_runtime.h>

// Problem constants
#define BF_TOT  (16 * 4096)      // B * F = 65536
#define PAIRS   6                // 12 data symbols -> 6 STBC pairs
#define NBITS0  3145728          // BF_TOT * 48
#define NGAIN   786432           // BF_TOT * 12

__device__ __forceinline__ float2 cmul (float2 a, float2 b){ return make_float2(a.x*b.x - a.y*b.y, a.x*b.y + a.y*b.x); }
__device__ __forceinline__ float2 cmulc(float2 a, float2 b){ /* conj(a)*b */ return make_float2(a.x*b.x + a.y*b.y, a.x*b.y - a.y*b.x); }
__device__ __forceinline__ float2 cadd (float2 a, float2 b){ return make_float2(a.x+b.x, a.y+b.y); }
__device__ __forceinline__ float2 csub (float2 a, float2 b){ return make_float2(a.x-b.x, a.y-b.y); }
__device__ __forceinline__ float2 cscl (float2 a, float s){ return make_float2(a.x*s, a.y*s); }
__device__ __forceinline__ float2 cconj(float2 a){ return make_float2(a.x, -a.y); }

// 16-QAM Gray hard decision with configurable magnitude threshold.
// Sign bits are scale-invariant; thr = (2/sqrt(10)) * input_scale.
// Output point is always canonical constellation scale.
__device__ __forceinline__ void hd16(float2 y, float thr, float2& pt, int& bits){
    const float C1 = 0.31622776601683794f;   // 1/sqrt(10)
    const float C3 = 0.9486832980505138f;    // 3/sqrt(10)
    int b0 = (y.x < 0.0f);
    int b1 = (y.y < 0.0f);
    int b2 = (fabsf(y.x) > thr);
    int b3 = (fabsf(y.y) > thr);
    float xi = b2 ? C3 : C1; if (b0) xi = -xi;
    float xq = b3 ? C3 : C1; if (b1) xq = -xq;
    pt = make_float2(xi, xq);
    bits = b0 | (b1 << 1) | (b2 << 2) | (b3 << 3);
}

// 3-step xor butterfly over each 8-lane group (result broadcast within group)
#define RED8(v) do { \
    v += __shfl_xor_sync(0xffffffffu, v, 1);  \
    v += __shfl_xor_sync(0xffffffffu, v, 2);  \
    v += __shfl_xor_sync(0xffffffffu, v, 4);  \
} while (0)

// Per-antenna Gram/rhs accumulation using channel SUMS (no 0.5; folded out).
#define GRAM_ACC(hrA_, hiA_, hrB_, hiB_, yA_, yB_) do {                         \
    float2 a_ = make_float2((hrA_).x+(hrB_).x, (hiA_).x+(hiB_).x);               \
    float2 b_ = make_float2((hrA_).y+(hrB_).y, (hiA_).y+(hiB_).y);               \
    float2 c_ = make_float2((hrA_).z+(hrB_).z, (hiA_).z+(hiB_).z);               \
    float2 d_ = make_float2((hrA_).w+(hrB_).w, (hiA_).w+(hiB_).w);               \
    alpha += a_.x*a_.x + a_.y*a_.y + b_.x*b_.x + b_.y*b_.y;                      \
    beta  += c_.x*c_.x + c_.y*c_.y + d_.x*d_.x + d_.y*d_.y;                      \
    gam = cadd(gam, cadd(cmulc(a_, c_), cmul(b_, cconj(d_))));                   \
    del = cadd(del, csub(cmulc(a_, d_), cmul(b_, cconj(c_))));                   \
    float2 z2_ = cconj(yB_);                                                     \
    u0 = cadd(u0, cadd(cmulc(a_, (yA_)), cmul(b_, z2_)));                        \
    u1 = cadd(u1, csub(cmulc(b_, (yA_)), cmul(a_, z2_)));                        \
    u2 = cadd(u2, cadd(cmulc(c_, (yA_)), cmul(d_, z2_)));                        \
    u3 = cadd(u3, csub(cmulc(d_, (yA_)), cmul(c_, z2_)));                        \
} while (0)

// Per-antenna SIC: cancellation uses RAW per-symbol channels (true scale);
// combining uses SUMMED worse channel (2x avg; folded into invG).
#define SIC_ACC(hrA_, hiA_, hrB_, hiB_, yA_, yB_) do {                           \
    float2 cbA0_, cbA1_, cbB0_, cbB1_, g0_, g1_;                                 \
    if (c0) {                                                                    \
        cbA0_ = make_float2((hrA_).x, (hiA_).x); cbA1_ = make_float2((hrA_).y, (hiA_).y); \
        cbB0_ = make_float2((hrB_).x, (hiB_).x); cbB1_ = make_float2((hrB_).y, (hiB_).y); \
        g0_ = make_float2((hrA_).z+(hrB_).z, (hiA_).z+(hiB_).z);                 \
        g1_ = make_float2((hrA_).w+(hrB_).w, (hiA_).w+(hiB_).w);                 \
    } else {                                                                     \
        cbA0_ = make_float2((hrA_).z, (hiA_).z); cbA1_ = make_float2((hrA_).w, (hiA_).w); \
        cbB0_ = make_float2((hrB_).z, (hiB_).z); cbB1_ = make_float2((hrB_).w, (hiB_).w); \
        g0_ = make_float2((hrA_).x+(hrB_).x, (hiA_).x+(hiB_).x);                 \
        g1_ = make_float2((hrA_).y+(hrB_).y, (hiA_).y+(hiB_).y);                 \
    }                                                                            \
    float2 eA_ = cadd(cmul(cbA0_, bx0), cmul(cbA1_, bx1));                       \
    float2 eB_ = cadd(cmul(cbB0_, mcbx1), cmul(cbB1_, cbx0));                    \
    float2 rnA_ = csub((yA_), eA_);                                              \
    float2 rnBc_ = cconj(csub((yB_), eB_));                                      \
    t0 = cadd(t0, cadd(cmulc(g0_, rnA_), cmul(g1_, rnBc_)));                     \
    t1 = cadd(t1, csub(cmulc(g1_, rnA_), cmul(g0_, rnBc_)));                     \
} while (0)

#define STRIDE 11   // float4 units; 8-lane phases hit banks (12*l)%32 -> 8 distinct

__global__ void __launch_bounds__(256, 4)
mc_ncjt_kernel(const float* __restrict__ ryR, const float* __restrict__ ryI,
               const float* __restrict__ hR,  const float* __restrict__ hI,
               float* __restrict__ out)
{
    // Per-thread stash of raw channel + received symbols; frees registers across
    // the reduction/solve so 4 CTAs/SM fit at 64 regs.
    __shared__ float4 stash[256][STRIDE];

    const int tid  = threadIdx.x;
    const int lane = tid & 31;
    const int warp = blockIdx.x * 8 + (tid >> 5);
    const int q    = lane >> 3;       // which pair within the warp (4 pairs/warp)
    const int j    = lane & 7;        // 8 lanes per pair; lane owns antennas j and j+8

    const int P  = warp * 4 + q;      // global STBC-pair index, exact grid
    const int bf = P / PAIRS;
    const int p  = P - bf * PAIRS;

    // data-symbol pairs: (0,1)(3,4)(5,6)(7,8)(9,10)(12,13)
    const int sA = 2*p + (p >= 1) + (p >= 5);
    const int sB = sA + 1;

    const float4* hR4 = (const float4*)hR;
    const float4* hI4 = (const float4*)hI;
    const size_t h4base = (size_t)bf * 224;          // bf * S*NRX*NTX / 4
    const size_t iA = h4base + (size_t)sA*16 + j;
    const size_t iB = h4base + (size_t)sB*16 + j;
    const size_t rb = (size_t)bf * 224;              // bf * S*NRX

    float alpha = 0.f, beta = 0.f;
    float2 gam = make_float2(0,0), del = make_float2(0,0);
    float2 u0 = make_float2(0,0), u1 = make_float2(0,0);
    float2 u2 = make_float2(0,0), u3 = make_float2(0,0);

    {   // scope raw h and y so their registers die after Gram accumulation
        float2 yA0 = make_float2(ryR[rb + sA*16 + j],     ryI[rb + sA*16 + j]);
        float2 yA1 = make_float2(ryR[rb + sA*16 + j + 8], ryI[rb + sA*16 + j + 8]);
        float2 yB0 = make_float2(ryR[rb + sB*16 + j],     ryI[rb + sB*16 + j]);
        float2 yB1 = make_float2(ryR[rb + sB*16 + j + 8], ryI[rb + sB*16 + j + 8]);
        float4 hrA0 = hR4[iA],     hrA1 = hR4[iA + 8];
        float4 hiA0 = hI4[iA],     hiA1 = hI4[iA + 8];
        float4 hrB0 = hR4[iB],     hrB1 = hR4[iB + 8];
        float4 hiB0 = hI4[iB],     hiB1 = hI4[iB + 8];
        stash[tid][0] = hrA0; stash[tid][1] = hiA0;
        stash[tid][2] = hrB0; stash[tid][3] = hiB0;
        stash[tid][4] = hrA1; stash[tid][5] = hiA1;
        stash[tid][6] = hrB1; stash[tid][7] = hiB1;
        stash[tid][8] = make_float4(yA0.x, yA0.y, yB0.x, yB0.y);
        stash[tid][9] = make_float4(yA1.x, yA1.y, yB1.x, yB1.y);
        GRAM_ACC(hrA0, hiA0, hrB0, hiB0, yA0, yB0);
        GRAM_ACC(hrA1, hiA1, hrB1, hiB1, yA1, yB1);
    }

    // ---- 8-lane reductions (broadcast within pair group) ----
    RED8(alpha); RED8(beta);
    RED8(gam.x); RED8(gam.y); RED8(del.x); RED8(del.y);
    RED8(u0.x);  RED8(u0.y);  RED8(u1.x);  RED8(u1.y);
    RED8(u2.x);  RED8(u2.y);  RED8(u3.x);  RED8(u3.y);

    // ---- closed-form Schur solve (scaled system: Ghat=4G, rhat=2r, shat=s/2) ----
    const float e      = gam.x*gam.x + gam.y*gam.y + del.x*del.x + del.y*del.y;
    const float invden = 1.0f / (alpha * beta - e);
    const float invA   = 1.0f / alpha;
    float2 t2 = csub(cscl(u2, alpha), csub(cmulc(gam, u0), cmul(del, u1)));
    float2 t3 = csub(cscl(u3, alpha), cadd(cmulc(del, u0), cmul(gam, u1)));
    float2 s2 = cscl(t2, invden);
    float2 s3 = cscl(t3, invden);
    float2 s0 = cscl(csub(u0, cadd(cmul(gam, s2), cmul(del, s3))), invA);
    float2 s1 = cscl(cadd(u1, csub(cmul(cconj(del), s2), cmul(cconj(gam), s3))), invA);

    const bool c0 = (alpha >= beta);

    // shat = s/2 -> magnitude threshold halves; bits/points otherwise identical
    const float THALF = 0.31622776601683794f;   // (2/sqrt(10)) / 2
    const float TFULL = 0.6324555320336759f;    //  2/sqrt(10)
    float2 px0, px1, px2, px3; int ib0, ib1, ib2, ib3;
    hd16(s0, THALF, px0, ib0); hd16(s1, THALF, px1, ib1);
    hd16(s2, THALF, px2, ib2); hd16(s3, THALF, px3, ib3);

    float2 bx0 = c0 ? px0 : px2;     // better-stream decisions (sym A, sym B)
    float2 bx1 = c0 ? px1 : px3;
    float2 mcbx1 = make_float2(-bx1.x, bx1.y);     // -conj(bx1)
    float2 cbx0  = cconj(bx0);

    // ---- SIC over this lane's 2 antennas (h and y reloaded from smem) ----
    float2 t0 = make_float2(0,0), t1 = make_float2(0,0);
    {
        float4 hrA0 = stash[tid][0], hiA0 = stash[tid][1];
        float4 hrB0 = stash[tid][2], hiB0 = stash[tid][3];
        float4 y0 = stash[tid][8];
        float2 yA0 = make_float2(y0.x, y0.y), yB0 = make_float2(y0.z, y0.w);
        SIC_ACC(hrA0, hiA0, hrB0, hiB0, yA0, yB0);
    }
    {
        float4 hrA1 = stash[tid][4], hiA1 = stash[tid][5];
        float4 hrB1 = stash[tid][6], hiB1 = stash[tid][7];
        float4 y1 = stash[tid][9];
        float2 yA1 = make_float2(y1.x, y1.y), yB1 = make_float2(y1.z, y1.w);
        SIC_ACC(hrA1, hiA1, hrB1, hiB1, yA1, yB1);
    }
    RED8(t0.x); RED8(t0.y); RED8(t1.x); RED8(t1.y);

    // that = 2t (summed worse channel); gain_true = alphahat/4 -> s = 2*that/ahat
    const float invG = 2.0f / (c0 ? beta : alpha);
    float2 pn0, pn1; int ibn0, ibn1;
    hd16(cscl(t0, invG), TFULL, pn0, ibn0);
    hd16(cscl(t1, invG), TFULL, pn1, ibn1);

    // final stream assignments
    const int bb0 = c0 ? ib0 : ib2;   // better bits sym A
    const int bb1 = c0 ? ib1 : ib3;   // better bits sym B
    const int b0A = c0 ? bb0  : ibn0; // bits0 (stream 0)
    const int b0B = c0 ? bb1  : ibn1;
    const int b1A = c0 ? ibn0 : bb0;  // bits1 (stream 1)
    const int b1B = c0 ? ibn1 : bb1;

    // ---- outputs: bits0 | bits1 | gains0 | gains1 | nvar ----
    float* bits0 = out;
    float* bits1 = out + NBITS0;
    float* g0out = out + 2 * NBITS0;
    float* g1out = out + 2 * NBITS0 + NGAIN;

    const int sym0 = 2 * p;
    const size_t bbase = (size_t)bf*48 + sym0*4;     // float4-aligned

    if (j < 4) {
        int nib = (j == 0) ? b0A : (j == 1) ? b0B : (j == 2) ? b1A : b1B;
        float4 v = make_float4((float)( nib       & 1), (float)((nib >> 1) & 1),
                               (float)((nib >> 2) & 1), (float)((nib >> 3) & 1));
        float* base = (j < 2) ? bits0 : bits1;
        *(float4*)(base + bbase + ((j & 1) << 2)) = v;
    } else if (j == 4) {
        float g = alpha * 0.25f;      // true gain (sum -> avg scale)
        *(float2*)(g0out + (size_t)bf*12 + sym0) = make_float2(g, g);
    } else if (j == 5) {
        float g = beta * 0.25f;
        *(float2*)(g1out + (size_t)bf*12 + sym0) = make_float2(g, g);
    }

    if (blockIdx.x == 0 && threadIdx.x == 0)
        out[2 * (NBITS0 + NGAIN)] = 0.4f;    // nvar scalar
}

extern "C" void kernel_launch(void* const* d_in, const int* in_sizes, int n_in,
                              void* d_out, int out_size) {
    const float* ryR = (const float*)d_in[0];
    const float* ryI = (const float*)d_in[1];
    const float* hR  = (const float*)d_in[2];
    const float* hI  = (const float*)d_in[3];
    float* out = (float*)d_out;

    // total pairs = 65536*6 = 393216; 4 pairs/warp, 8 warps/block -> 12288 blocks
    const int total_pairs = BF_TOT * PAIRS;
    const int blocks = total_pairs / 32;   // 32 pairs per 256-thread block
    mc_ncjt_kernel<<<blocks, 256>>>(ryR, ryI, hR, hI, out);
}

// round 9
// speedup vs baseline: 2.5661x; 1.6495x over previous
#include <cuda_runtime.h>

// Problem constants
#define BF_TOT  (16 * 4096)      // B * F = 65536
#define PAIRS   6                // 12 data symbols -> 6 STBC pairs
#define NBITS0  3145728          // BF_TOT * 48
#define NGAIN   786432           // BF_TOT * 12

__device__ __forceinline__ float2 cmul (float2 a, float2 b){ return make_float2(a.x*b.x - a.y*b.y, a.x*b.y + a.y*b.x); }
__device__ __forceinline__ float2 cmulc(float2 a, float2 b){ /* conj(a)*b */ return make_float2(a.x*b.x + a.y*b.y, a.x*b.y - a.y*b.x); }
__device__ __forceinline__ float2 cadd (float2 a, float2 b){ return make_float2(a.x+b.x, a.y+b.y); }
__device__ __forceinline__ float2 csub (float2 a, float2 b){ return make_float2(a.x-b.x, a.y-b.y); }
__device__ __forceinline__ float2 cscl (float2 a, float s){ return make_float2(a.x*s, a.y*s); }
__device__ __forceinline__ float2 cconj(float2 a){ return make_float2(a.x, -a.y); }

// 16-QAM Gray hard decision with configurable magnitude threshold.
// Sign bits are scale-invariant; thr = (2/sqrt(10)) * input_scale.
__device__ __forceinline__ void hd16(float2 y, float thr, float2& pt, int& bits){
    const float C1 = 0.31622776601683794f;   // 1/sqrt(10)
    const float C3 = 0.9486832980505138f;    // 3/sqrt(10)
    int b0 = (y.x < 0.0f);
    int b1 = (y.y < 0.0f);
    int b2 = (fabsf(y.x) > thr);
    int b3 = (fabsf(y.y) > thr);
    float xi = b2 ? C3 : C1; if (b0) xi = -xi;
    float xq = b3 ? C3 : C1; if (b1) xq = -xq;
    pt = make_float2(xi, xq);
    bits = b0 | (b1 << 1) | (b2 << 2) | (b3 << 3);
}

// 3-step xor butterfly over each 8-lane group (result broadcast within group)
#define RED8(v) do { \
    v += __shfl_xor_sync(0xffffffffu, v, 1);  \
    v += __shfl_xor_sync(0xffffffffu, v, 2);  \
    v += __shfl_xor_sync(0xffffffffu, v, 4);  \
} while (0)

// Per-antenna Gram/rhs accumulation using channel SUMS (0.5 folded out).
#define GRAM_ACC(hrA_, hiA_, hrB_, hiB_, yA_, yB_) do {                         \
    float2 a_ = make_float2((hrA_).x+(hrB_).x, (hiA_).x+(hiB_).x);               \
    float2 b_ = make_float2((hrA_).y+(hrB_).y, (hiA_).y+(hiB_).y);               \
    float2 c_ = make_float2((hrA_).z+(hrB_).z, (hiA_).z+(hiB_).z);               \
    float2 d_ = make_float2((hrA_).w+(hrB_).w, (hiA_).w+(hiB_).w);               \
    alpha += a_.x*a_.x + a_.y*a_.y + b_.x*b_.x + b_.y*b_.y;                      \
    beta  += c_.x*c_.x + c_.y*c_.y + d_.x*d_.x + d_.y*d_.y;                      \
    gam = cadd(gam, cadd(cmulc(a_, c_), cmul(b_, cconj(d_))));                   \
    del = cadd(del, csub(cmulc(a_, d_), cmul(b_, cconj(c_))));                   \
    float2 z2_ = cconj(yB_);                                                     \
    u0 = cadd(u0, cadd(cmulc(a_, (yA_)), cmul(b_, z2_)));                        \
    u1 = cadd(u1, csub(cmulc(b_, (yA_)), cmul(a_, z2_)));                        \
    u2 = cadd(u2, cadd(cmulc(c_, (yA_)), cmul(d_, z2_)));                        \
    u3 = cadd(u3, csub(cmulc(d_, (yA_)), cmul(c_, z2_)));                        \
} while (0)

// Per-antenna SIC: cancellation uses RAW per-symbol channels (true scale);
// combining uses SUMMED worse channel (2x avg; folded into invG).
#define SIC_ACC(hrA_, hiA_, hrB_, hiB_, yA_, yB_) do {                           \
    float2 cbA0_, cbA1_, cbB0_, cbB1_, g0_, g1_;                                 \
    if (c0) {                                                                    \
        cbA0_ = make_float2((hrA_).x, (hiA_).x); cbA1_ = make_float2((hrA_).y, (hiA_).y); \
        cbB0_ = make_float2((hrB_).x, (hiB_).x); cbB1_ = make_float2((hrB_).y, (hiB_).y); \
        g0_ = make_float2((hrA_).z+(hrB_).z, (hiA_).z+(hiB_).z);                 \
        g1_ = make_float2((hrA_).w+(hrB_).w, (hiA_).w+(hiB_).w);                 \
    } else {                                                                     \
        cbA0_ = make_float2((hrA_).z, (hiA_).z); cbA1_ = make_float2((hrA_).w, (hiA_).w); \
        cbB0_ = make_float2((hrB_).z, (hiB_).z); cbB1_ = make_float2((hrB_).w, (hiB_).w); \
        g0_ = make_float2((hrA_).x+(hrB_).x, (hiA_).x+(hiB_).x);                 \
        g1_ = make_float2((hrA_).y+(hrB_).y, (hiA_).y+(hiB_).y);                 \
    }                                                                            \
    float2 eA_ = cadd(cmul(cbA0_, bx0), cmul(cbA1_, bx1));                       \
    float2 eB_ = cadd(cmul(cbB0_, mcbx1), cmul(cbB1_, cbx0));                    \
    float2 rnA_ = csub((yA_), eA_);                                              \
    float2 rnBc_ = cconj(csub((yB_), eB_));                                      \
    t0 = cadd(t0, cadd(cmulc(g0_, rnA_), cmul(g1_, rnBc_)));                     \
    t1 = cadd(t1, csub(cmulc(g1_, rnA_), cmul(g0_, rnBc_)));                     \
} while (0)

__global__ void __launch_bounds__(256, 3)
mc_ncjt_kernel(const float* __restrict__ ryR, const float* __restrict__ ryI,
               const float* __restrict__ hR,  const float* __restrict__ hI,
               float* __restrict__ out)
{
    // Per-thread stash of raw channel data (frees 32 regs across the reduction).
    // Stride 9 float4 (144B): 8-lane phases hit banks (36*l + 4k)%32, distinct.
    __shared__ float4 stash[256][9];

    const int tid  = threadIdx.x;
    const int lane = tid & 31;
    const int warp = blockIdx.x * 8 + (tid >> 5);
    const int q    = lane >> 3;       // which pair within the warp (4 pairs/warp)
    const int j    = lane & 7;        // 8 lanes per pair; lane owns antennas j and j+8

    const int P  = warp * 4 + q;      // global STBC-pair index, exact grid
    const int bf = P / PAIRS;
    const int p  = P - bf * PAIRS;

    // data-symbol pairs: (0,1)(3,4)(5,6)(7,8)(9,10)(12,13)
    const int sA = 2*p + (p >= 1) + (p >= 5);
    const int sB = sA + 1;

    const float4* hR4 = (const float4*)hR;
    const float4* hI4 = (const float4*)hI;
    const size_t h4base = (size_t)bf * 224;          // bf * S*NRX*NTX / 4
    const size_t iA = h4base + (size_t)sA*16 + j;
    const size_t iB = h4base + (size_t)sB*16 + j;
    const size_t rb = (size_t)bf * 224;              // bf * S*NRX

    // streaming (evict-first) loads: every input byte is read exactly once
    float2 yA0 = make_float2(__ldcs(ryR + rb + sA*16 + j),     __ldcs(ryI + rb + sA*16 + j));
    float2 yA1 = make_float2(__ldcs(ryR + rb + sA*16 + j + 8), __ldcs(ryI + rb + sA*16 + j + 8));
    float2 yB0 = make_float2(__ldcs(ryR + rb + sB*16 + j),     __ldcs(ryI + rb + sB*16 + j));
    float2 yB1 = make_float2(__ldcs(ryR + rb + sB*16 + j + 8), __ldcs(ryI + rb + sB*16 + j + 8));

    float alpha = 0.f, beta = 0.f;
    float2 gam = make_float2(0,0), del = make_float2(0,0);
    float2 u0 = make_float2(0,0), u1 = make_float2(0,0);
    float2 u2 = make_float2(0,0), u3 = make_float2(0,0);

    {   // scope raw h so the registers die after Gram accumulation
        float4 hrA0 = __ldcs(hR4 + iA),     hrA1 = __ldcs(hR4 + iA + 8);
        float4 hiA0 = __ldcs(hI4 + iA),     hiA1 = __ldcs(hI4 + iA + 8);
        float4 hrB0 = __ldcs(hR4 + iB),     hrB1 = __ldcs(hR4 + iB + 8);
        float4 hiB0 = __ldcs(hI4 + iB),     hiB1 = __ldcs(hI4 + iB + 8);
        stash[tid][0] = hrA0; stash[tid][1] = hiA0;
        stash[tid][2] = hrB0; stash[tid][3] = hiB0;
        stash[tid][4] = hrA1; stash[tid][5] = hiA1;
        stash[tid][6] = hrB1; stash[tid][7] = hiB1;
        GRAM_ACC(hrA0, hiA0, hrB0, hiB0, yA0, yB0);
        GRAM_ACC(hrA1, hiA1, hrB1, hiB1, yA1, yB1);
    }

    // ---- 8-lane reductions (broadcast within pair group) ----
    RED8(alpha); RED8(beta);
    RED8(gam.x); RED8(gam.y); RED8(del.x); RED8(del.y);
    RED8(u0.x);  RED8(u0.y);  RED8(u1.x);  RED8(u1.y);
    RED8(u2.x);  RED8(u2.y);  RED8(u3.x);  RED8(u3.y);

    // ---- closed-form Schur solve (scaled: Ghat=4G, rhat=2r -> shat=s/2) ----
    const float e      = gam.x*gam.x + gam.y*gam.y + del.x*del.x + del.y*del.y;
    const float invden = 1.0f / (alpha * beta - e);
    const float invA   = 1.0f / alpha;
    float2 t2 = csub(cscl(u2, alpha), csub(cmulc(gam, u0), cmul(del, u1)));
    float2 t3 = csub(cscl(u3, alpha), cadd(cmulc(del, u0), cmul(gam, u1)));
    float2 s2 = cscl(t2, invden);
    float2 s3 = cscl(t3, invden);
    float2 s0 = cscl(csub(u0, cadd(cmul(gam, s2), cmul(del, s3))), invA);
    float2 s1 = cscl(cadd(u1, csub(cmul(cconj(del), s2), cmul(cconj(gam), s3))), invA);

    const bool c0 = (alpha >= beta);

    // shat = s/2 -> magnitude threshold halves; bits/points otherwise identical
    const float THALF = 0.31622776601683794f;   // (2/sqrt(10)) / 2
    const float TFULL = 0.6324555320336759f;    //  2/sqrt(10)
    float2 px0, px1, px2, px3; int ib0, ib1, ib2, ib3;
    hd16(s0, THALF, px0, ib0); hd16(s1, THALF, px1, ib1);
    hd16(s2, THALF, px2, ib2); hd16(s3, THALF, px3, ib3);

    float2 bx0 = c0 ? px0 : px2;     // better-stream decisions (sym A, sym B)
    float2 bx1 = c0 ? px1 : px3;
    float2 mcbx1 = make_float2(-bx1.x, bx1.y);     // -conj(bx1)
    float2 cbx0  = cconj(bx0);

    // ---- SIC over this lane's 2 antennas (raw h reloaded from smem) ----
    float2 t0 = make_float2(0,0), t1 = make_float2(0,0);
    {
        float4 hrA0 = stash[tid][0], hiA0 = stash[tid][1];
        float4 hrB0 = stash[tid][2], hiB0 = stash[tid][3];
        SIC_ACC(hrA0, hiA0, hrB0, hiB0, yA0, yB0);
    }
    {
        float4 hrA1 = stash[tid][4], hiA1 = stash[tid][5];
        float4 hrB1 = stash[tid][6], hiB1 = stash[tid][7];
        SIC_ACC(hrA1, hiA1, hrB1, hiB1, yA1, yB1);
    }
    RED8(t0.x); RED8(t0.y); RED8(t1.x); RED8(t1.y);

    // that = 2t (summed worse channel); true gain = betahat/4 -> y = 2*that/bhat
    const float invG = 2.0f / (c0 ? beta : alpha);
    float2 pn0, pn1; int ibn0, ibn1;
    hd16(cscl(t0, invG), TFULL, pn0, ibn0);
    hd16(cscl(t1, invG), TFULL, pn1, ibn1);

    // final stream assignments
    const int bb0 = c0 ? ib0 : ib2;   // better bits sym A
    const int bb1 = c0 ? ib1 : ib3;   // better bits sym B
    const int b0A = c0 ? bb0  : ibn0; // bits0 (stream 0)
    const int b0B = c0 ? bb1  : ibn1;
    const int b1A = c0 ? ibn0 : bb0;  // bits1 (stream 1)
    const int b1B = c0 ? ibn1 : bb1;

    // ---- outputs: bits0 | bits1 | gains0 | gains1 | nvar ----
    float* bits0 = out;
    float* bits1 = out + NBITS0;
    float* g0out = out + 2 * NBITS0;
    float* g1out = out + 2 * NBITS0 + NGAIN;

    const int sym0 = 2 * p;
    const size_t bbase = (size_t)bf*48 + sym0*4;     // float4-aligned

    if (j < 4) {
        int nib = (j == 0) ? b0A : (j == 1) ? b0B : (j == 2) ? b1A : b1B;
        float4 v = make_float4((float)( nib       & 1), (float)((nib >> 1) & 1),
                               (float)((nib >> 2) & 1), (float)((nib >> 3) & 1));
        float* base = (j < 2) ? bits0 : bits1;
        *(float4*)(base + bbase + ((j & 1) << 2)) = v;
    } else if (j == 4) {
        float g = alpha * 0.25f;      // true gain (sum -> avg scale)
        *(float2*)(g0out + (size_t)bf*12 + sym0) = make_float2(g, g);
    } else if (j == 5) {
        float g = beta * 0.25f;
        *(float2*)(g1out + (size_t)bf*12 + sym0) = make_float2(g, g);
    }

    if (blockIdx.x == 0 && threadIdx.x == 0)
        out[2 * (NBITS0 + NGAIN)] = 0.4f;    // nvar scalar
}

extern "C" void kernel_launch(void* const* d_in, const int* in_sizes, int n_in,
                              void* d_out, int out_size) {
    const float* ryR = (const float*)d_in[0];
    const float* ryI = (const float*)d_in[1];
    const float* hR  = (const float*)d_in[2];
    const float* hI  = (const float*)d_in[3];
    float* out = (float*)d_out;

    // total pairs = 65536*6 = 393216; 4 pairs/warp, 8 warps/block -> 12288 blocks
    const int total_pairs = BF_TOT * PAIRS;
    const int blocks = total_pairs / 32;   // 32 pairs per 256-thread block
    mc_ncjt_kernel<<<blocks, 256>>>(ryR, ryI, hR, hI, out);
}

// round 11
// speedup vs baseline: 2.7995x; 1.0910x over previous
#include <cuda_runtime.h>

// Problem constants
#define BF_TOT  (16 * 4096)      // B * F = 65536
#define PAIRS   6                // 12 data symbols -> 6 STBC pairs
#define NBITS0  3145728          // BF_TOT * 48
#define NGAIN   786432           // BF_TOT * 12

typedef unsigned long long u64;

// ---- packed f32x2 primitives (sm_100+/sm_103a) ----
__device__ __forceinline__ u64 pk(float lo, float hi){
    u64 r; asm("mov.b64 %0, {%1, %2};" : "=l"(r) : "f"(lo), "f"(hi)); return r;
}
__device__ __forceinline__ float usum(u64 v){
    float lo, hi; asm("mov.b64 {%0, %1}, %2;" : "=f"(lo), "=f"(hi) : "l"(v));
    return lo + hi;
}
__device__ __forceinline__ u64 fmul2(u64 a, u64 b){
    u64 d; asm("mul.rn.f32x2 %0, %1, %2;" : "=l"(d) : "l"(a), "l"(b)); return d;
}
__device__ __forceinline__ u64 fadd2(u64 a, u64 b){
    u64 d; asm("add.rn.f32x2 %0, %1, %2;" : "=l"(d) : "l"(a), "l"(b)); return d;
}
__device__ __forceinline__ u64 fsub2(u64 a, u64 b){
    u64 d; asm("sub.rn.f32x2 %0, %1, %2;" : "=l"(d) : "l"(a), "l"(b)); return d;
}
__device__ __forceinline__ u64 ffma2(u64 a, u64 b, u64 c){
    u64 d; asm("fma.rn.f32x2 %0, %1, %2, %3;" : "=l"(d) : "l"(a), "l"(b), "l"(c)); return d;
}
// a*b + c*d
__device__ __forceinline__ u64 dot2(u64 a, u64 b, u64 c, u64 d){
    return ffma2(c, d, fmul2(a, b));
}
// a*b + c*d + e*f + g*h
__device__ __forceinline__ u64 dot4(u64 a,u64 b,u64 c,u64 d,u64 e,u64 f,u64 g,u64 h){
    return ffma2(g, h, ffma2(e, f, ffma2(c, d, fmul2(a, b))));
}

// ---- scalar complex helpers (solve path) ----
__device__ __forceinline__ float2 cmul (float2 a, float2 b){ return make_float2(a.x*b.x - a.y*b.y, a.x*b.y + a.y*b.x); }
__device__ __forceinline__ float2 cmulc(float2 a, float2 b){ return make_float2(a.x*b.x + a.y*b.y, a.x*b.y - a.y*b.x); }
__device__ __forceinline__ float2 cadd (float2 a, float2 b){ return make_float2(a.x+b.x, a.y+b.y); }
__device__ __forceinline__ float2 csub (float2 a, float2 b){ return make_float2(a.x-b.x, a.y-b.y); }
__device__ __forceinline__ float2 cscl (float2 a, float s){ return make_float2(a.x*s, a.y*s); }
__device__ __forceinline__ float2 cconj(float2 a){ return make_float2(a.x, -a.y); }

// 16-QAM Gray hard decision with configurable magnitude threshold.
__device__ __forceinline__ void hd16(float2 y, float thr, float2& pt, int& bits){
    const float C1 = 0.31622776601683794f;   // 1/sqrt(10)
    const float C3 = 0.9486832980505138f;    // 3/sqrt(10)
    int b0 = (y.x < 0.0f);
    int b1 = (y.y < 0.0f);
    int b2 = (fabsf(y.x) > thr);
    int b3 = (fabsf(y.y) > thr);
    float xi = b2 ? C3 : C1; if (b0) xi = -xi;
    float xq = b3 ? C3 : C1; if (b1) xq = -xq;
    pt = make_float2(xi, xq);
    bits = b0 | (b1 << 1) | (b2 << 2) | (b3 << 3);
}

// 3-step xor butterfly over each 8-lane group (result broadcast within group)
#define RED8(v) do { \
    v += __shfl_xor_sync(0xffffffffu, v, 1);  \
    v += __shfl_xor_sync(0xffffffffu, v, 2);  \
    v += __shfl_xor_sync(0xffffffffu, v, 4);  \
} while (0)

__global__ void __launch_bounds__(256, 3)
mc_ncjt_kernel(const float* __restrict__ ryR, const float* __restrict__ ryI,
               const float* __restrict__ hR,  const float* __restrict__ hI,
               float* __restrict__ out)
{
    // Packed raw channel stash: slot-major [8][256] ulonglong2 -> conflict-free
    // LDS/STS.128 (banks 4*tid%32, each 8-lane phase covers all 32 banks once).
    // Slots: pA(aRI,bRI,cRI,dRI)=0..3, pB(...)=4..7.  32 KB/block.
    __shared__ ulonglong2 pst[8][256];

    const int tid  = threadIdx.x;
    const int lane = tid & 31;
    const unsigned warp = blockIdx.x * 8u + (unsigned)(tid >> 5);
    const int q    = lane >> 3;       // which pair within the warp (4 pairs/warp)
    const int j    = lane & 7;        // 8 lanes per pair; lane owns antennas j and j+8

    const unsigned P  = warp * 4u + (unsigned)q;   // global STBC-pair index
    const unsigned bf = P / PAIRS;
    const unsigned p  = P - bf * PAIRS;

    // data-symbol pairs: (0,1)(3,4)(5,6)(7,8)(9,10)(12,13)
    const unsigned sA = 2u*p + (p >= 1u) + (p >= 5u);
    const unsigned sB = sA + 1u;

    const float4* hR4 = (const float4*)hR;
    const float4* hI4 = (const float4*)hI;
    const unsigned h4base = bf * 224u;          // bf * S*NRX*NTX / 4
    const unsigned iA = h4base + sA*16u + (unsigned)j;
    const unsigned iB = h4base + sB*16u + (unsigned)j;
    const unsigned rb = bf * 224u;              // bf * S*NRX

    // ---- streaming loads ----
    float2 yA0 = make_float2(__ldcs(ryR + rb + sA*16u + j),      __ldcs(ryI + rb + sA*16u + j));
    float2 yA1 = make_float2(__ldcs(ryR + rb + sA*16u + j + 8),  __ldcs(ryI + rb + sA*16u + j + 8));
    float2 yB0 = make_float2(__ldcs(ryR + rb + sB*16u + j),      __ldcs(ryI + rb + sB*16u + j));
    float2 yB1 = make_float2(__ldcs(ryR + rb + sB*16u + j + 8),  __ldcs(ryI + rb + sB*16u + j + 8));

    float4 hrA0 = __ldcs(hR4 + iA),     hrA1 = __ldcs(hR4 + iA + 8);
    float4 hiA0 = __ldcs(hI4 + iA),     hiA1 = __ldcs(hI4 + iA + 8);
    float4 hrB0 = __ldcs(hR4 + iB),     hrB1 = __ldcs(hR4 + iB + 8);
    float4 hiB0 = __ldcs(hI4 + iB),     hiB1 = __ldcs(hI4 + iB + 8);

    // ---- pack per-antenna pairs: (antenna j, antenna j+8) as f32x2 ----
    u64 pAaR = pk(hrA0.x, hrA1.x), pAaI = pk(hiA0.x, hiA1.x);
    u64 pAbR = pk(hrA0.y, hrA1.y), pAbI = pk(hiA0.y, hiA1.y);
    u64 pAcR = pk(hrA0.z, hrA1.z), pAcI = pk(hiA0.z, hiA1.z);
    u64 pAdR = pk(hrA0.w, hrA1.w), pAdI = pk(hiA0.w, hiA1.w);
    u64 pBaR = pk(hrB0.x, hrB1.x), pBaI = pk(hiB0.x, hiB1.x);
    u64 pBbR = pk(hrB0.y, hrB1.y), pBbI = pk(hiB0.y, hiB1.y);
    u64 pBcR = pk(hrB0.z, hrB1.z), pBcI = pk(hiB0.z, hiB1.z);
    u64 pBdR = pk(hrB0.w, hrB1.w), pBdI = pk(hiB0.w, hiB1.w);

    // stash raw packed channel for the SIC pass (frees the registers)
    pst[0][tid] = make_ulonglong2(pAaR, pAaI);
    pst[1][tid] = make_ulonglong2(pAbR, pAbI);
    pst[2][tid] = make_ulonglong2(pAcR, pAcI);
    pst[3][tid] = make_ulonglong2(pAdR, pAdI);
    pst[4][tid] = make_ulonglong2(pBaR, pBaI);
    pst[5][tid] = make_ulonglong2(pBbR, pBbI);
    pst[6][tid] = make_ulonglong2(pBcR, pBcI);
    pst[7][tid] = make_ulonglong2(pBdR, pBdI);

    // summed channel (2x average; scale folded into thresholds/invG/gains)
    u64 aR = fadd2(pAaR, pBaR), aI = fadd2(pAaI, pBaI);
    u64 bR = fadd2(pAbR, pBbR), bI = fadd2(pAbI, pBbI);
    u64 cR = fadd2(pAcR, pBcR), cI = fadd2(pAcI, pBcI);
    u64 dR = fadd2(pAdR, pBdR), dI = fadd2(pAdI, pBdI);

    u64 yAr = pk(yA0.x, yA1.x), yAi = pk(yA0.y, yA1.y);
    u64 yBr = pk(yB0.x, yB1.x), yBi = pk(yB0.y, yB1.y);

    // ---- packed Gram/rhs (both antennas at once), unpack to scalars ----
    float alpha = usum(dot4(aR,aR, aI,aI, bR,bR, bI,bI));
    float beta  = usum(dot4(cR,cR, cI,cI, dR,dR, dI,dI));
    float2 gam, del, u0, u1, u2, u3;
    gam.x = usum(dot4(aR,cR, aI,cI, bR,dR, bI,dI));
    gam.y = usum(fsub2(dot2(aR,cI, bI,dR), dot2(aI,cR, bR,dI)));
    del.x = usum(fsub2(dot2(aR,dR, aI,dI), dot2(bR,cR, bI,cI)));
    del.y = usum(fsub2(dot2(aR,dI, bR,cI), dot2(aI,dR, bI,cR)));
    u0.x  = usum(dot4(aR,yAr, aI,yAi, bR,yBr, bI,yBi));
    u0.y  = usum(fsub2(dot2(aR,yAi, bI,yBr), dot2(aI,yAr, bR,yBi)));
    u1.x  = usum(fsub2(dot2(bR,yAr, bI,yAi), dot2(aR,yBr, aI,yBi)));
    u1.y  = usum(fsub2(dot2(bR,yAi, aR,yBi), dot2(bI,yAr, aI,yBr)));
    u2.x  = usum(dot4(cR,yAr, cI,yAi, dR,yBr, dI,yBi));
    u2.y  = usum(fsub2(dot2(cR,yAi, dI,yBr), dot2(cI,yAr, dR,yBi)));
    u3.x  = usum(fsub2(dot2(dR,yAr, dI,yAi), dot2(cR,yBr, cI,yBi)));
    u3.y  = usum(fsub2(dot2(dR,yAi, cR,yBi), dot2(dI,yAr, cI,yBr)));

    // ---- 8-lane reductions (broadcast within pair group) ----
    RED8(alpha); RED8(beta);
    RED8(gam.x); RED8(gam.y); RED8(del.x); RED8(del.y);
    RED8(u0.x);  RED8(u0.y);  RED8(u1.x);  RED8(u1.y);
    RED8(u2.x);  RED8(u2.y);  RED8(u3.x);  RED8(u3.y);

    // ---- closed-form Schur solve (scaled: Ghat=4G, uhat=2u -> shat=s/2) ----
    const float e      = gam.x*gam.x + gam.y*gam.y + del.x*del.x + del.y*del.y;
    const float invden = 1.0f / (alpha * beta - e);
    const float invA   = 1.0f / alpha;
    float2 t2 = csub(cscl(u2, alpha), csub(cmulc(gam, u0), cmul(del, u1)));
    float2 t3 = csub(cscl(u3, alpha), cadd(cmulc(del, u0), cmul(gam, u1)));
    float2 s2 = cscl(t2, invden);
    float2 s3 = cscl(t3, invden);
    float2 s0 = cscl(csub(u0, cadd(cmul(gam, s2), cmul(del, s3))), invA);
    float2 s1 = cscl(cadd(u1, csub(cmul(cconj(del), s2), cmul(cconj(gam), s3))), invA);

    const bool c0 = (alpha >= beta);

    const float THALF = 0.31622776601683794f;   // (2/sqrt(10)) / 2
    const float TFULL = 0.6324555320336759f;    //  2/sqrt(10)
    float2 px0, px1, px2, px3; int ib0, ib1, ib2, ib3;
    hd16(s0, THALF, px0, ib0); hd16(s1, THALF, px1, ib1);
    hd16(s2, THALF, px2, ib2); hd16(s3, THALF, px3, ib3);

    float2 bx0 = c0 ? px0 : px2;     // better-stream decisions (sym A, sym B)
    float2 bx1 = c0 ? px1 : px3;

    // broadcast decisions into packed form
    u64 B0R = pk(bx0.x, bx0.x), B0I = pk(bx0.y, bx0.y);
    u64 B1R = pk(bx1.x, bx1.x), B1I = pk(bx1.y, bx1.y);

    // ---- SIC (packed): reload raw channel from smem, cancel, recombine ----
    ulonglong2 cbA0 = pst[c0 ? 0 : 2][tid];   // better ch, sym A, first TX
    ulonglong2 cbA1 = pst[c0 ? 1 : 3][tid];
    ulonglong2 cbB0 = pst[c0 ? 4 : 6][tid];
    ulonglong2 cbB1 = pst[c0 ? 5 : 7][tid];
    ulonglong2 wA0  = pst[c0 ? 2 : 0][tid];   // worse ch, sym A
    ulonglong2 wA1  = pst[c0 ? 3 : 1][tid];
    ulonglong2 wB0  = pst[c0 ? 6 : 4][tid];
    ulonglong2 wB1  = pst[c0 ? 7 : 5][tid];
    u64 g0R = fadd2(wA0.x, wB0.x), g0I = fadd2(wA0.y, wB0.y);
    u64 g1R = fadd2(wA1.x, wB1.x), g1I = fadd2(wA1.y, wB1.y);

    // eA = cbA0*bx0 + cbA1*bx1
    u64 eAr = fsub2(dot2(cbA0.x,B0R, cbA1.x,B1R), dot2(cbA0.y,B0I, cbA1.y,B1I));
    u64 eAi = dot4(cbA0.x,B0I, cbA0.y,B0R, cbA1.x,B1I, cbA1.y,B1R);
    // eB = cbB0*(-conj(bx1)) + cbB1*conj(bx0)
    u64 eBr = fsub2(dot2(cbB1.x,B0R, cbB1.y,B0I), dot2(cbB0.x,B1R, cbB0.y,B1I));
    u64 eBi = fsub2(dot2(cbB0.x,B1I, cbB1.y,B0R), dot2(cbB0.y,B1R, cbB1.x,B0I));
    u64 rnAr = fsub2(yAr, eAr), rnAi = fsub2(yAi, eAi);
    u64 rnBr = fsub2(yBr, eBr), rnBi = fsub2(yBi, eBi);

    // t0 = conj(g0)*rnA + g1*conj(rnB); t1 = conj(g1)*rnA - g0*conj(rnB)
    float2 t0, t1;
    t0.x = usum(dot4(g0R,rnAr, g0I,rnAi, g1R,rnBr, g1I,rnBi));
    t0.y = usum(fsub2(dot2(g0R,rnAi, g1I,rnBr), dot2(g0I,rnAr, g1R,rnBi)));
    t1.x = usum(fsub2(dot2(g1R,rnAr, g1I,rnAi), dot2(g0R,rnBr, g0I,rnBi)));
    t1.y = usum(fsub2(dot2(g1R,rnAi, g0R,rnBi), dot2(g1I,rnAr, g0I,rnBr)));
    RED8(t0.x); RED8(t0.y); RED8(t1.x); RED8(t1.y);

    // g summed = 2x avg; true gain = betahat/4 -> y = 2*that/betahat
    const float invG = 2.0f / (c0 ? beta : alpha);
    float2 pn0, pn1; int ibn0, ibn1;
    hd16(cscl(t0, invG), TFULL, pn0, ibn0);
    hd16(cscl(t1, invG), TFULL, pn1, ibn1);

    // final stream assignments
    const int bb0 = c0 ? ib0 : ib2;   // better bits sym A
    const int bb1 = c0 ? ib1 : ib3;   // better bits sym B
    const int b0A = c0 ? bb0  : ibn0; // bits0 (stream 0)
    const int b0B = c0 ? bb1  : ibn1;
    const int b1A = c0 ? ibn0 : bb0;  // bits1 (stream 1)
    const int b1B = c0 ? ibn1 : bb1;

    // ---- outputs: bits0 | bits1 | gains0 | gains1 | nvar ----
    float* bits0 = out;
    float* bits1 = out + NBITS0;
    float* g0out = out + 2 * NBITS0;
    float* g1out = out + 2 * NBITS0 + NGAIN;

    const unsigned sym0 = 2u * p;
    const unsigned bbase = bf*48u + sym0*4u;     // float4-aligned

    if (j < 4) {
        int nib = (j == 0) ? b0A : (j == 1) ? b0B : (j == 2) ? b1A : b1B;
        float4 v = make_float4((float)( nib       & 1), (float)((nib >> 1) & 1),
                               (float)((nib >> 2) & 1), (float)((nib >> 3) & 1));
        float* base = (j < 2) ? bits0 : bits1;
        *(float4*)(base + bbase + ((j & 1) << 2)) = v;
    } else if (j == 4) {
        float g = alpha * 0.25f;      // true gain (sum -> avg scale)
        *(float2*)(g0out + bf*12u + sym0) = make_float2(g, g);
    } else if (j == 5) {
        float g = beta * 0.25f;
        *(float2*)(g1out + bf*12u + sym0) = make_float2(g, g);
    }

    if (blockIdx.x == 0 && threadIdx.x == 0)
        out[2 * (NBITS0 + NGAIN)] = 0.4f;    // nvar scalar
}

extern "C" void kernel_launch(void* const* d_in, const int* in_sizes, int n_in,
                              void* d_out, int out_size) {
    const float* ryR = (const float*)d_in[0];
    const float* ryI = (const float*)d_in[1];
    const float* hR  = (const float*)d_in[2];
    const float* hI  = (const float*)d_in[3];
    float* out = (float*)d_out;

    // total pairs = 65536*6 = 393216; 4 pairs/warp, 8 warps/block -> 12288 blocks
    const int total_pairs = BF_TOT * PAIRS;
    const int blocks = total_pairs / 32;   // 32 pairs per 256-thread block
    mc_ncjt_kernel<<<blocks, 256>>>(ryR, ryI, hR, hI, out);
}